// round 11
// baseline (speedup 1.0000x reference)
#include <cuda_runtime.h>
#include <math.h>

// dims: (1,1,D=160,H=192,W=160), x fastest
#define DW 160
#define DH 192
#define DD 160
#define SLICE (DH*DW)
#define NVOX (DD*SLICE)

#define TX 32
#define TY 16
#define CZ 16
#define SMW (TX+2)
#define SMH (TY+2)
#define NTHREADS (TX*TY)      // 512
#define GXD (DW/TX)   // 5
#define GYD (DH/TY)   // 12
#define GZD (DD/CZ)   // 10
#define NBLOCKS (GXD*GYD*GZD)   // 600
#define FEPS 1e-10f

#define NBUF 6
#define CELLS (SMH*SMW)       // 612
#define BUFBYTES (CELLS*8)

typedef unsigned long long u64;

// packed (lo,hi) f32x2 helpers — FFMA2/FADD2 only reachable via PTX
__device__ __forceinline__ u64 pk2(float lo, float hi) {
    u64 r; asm("mov.b64 %0, {%1, %2};" : "=l"(r) : "f"(lo), "f"(hi)); return r;
}
__device__ __forceinline__ void upk2(u64 v, float& lo, float& hi) {
    asm("mov.b64 {%0, %1}, %2;" : "=f"(lo), "=f"(hi) : "l"(v));
}
__device__ __forceinline__ u64 fma2(u64 a, u64 b, u64 c) {
    u64 d; asm("fma.rn.f32x2 %0, %1, %2, %3;" : "=l"(d) : "l"(a), "l"(b), "l"(c)); return d;
}
__device__ __forceinline__ u64 add2(u64 a, u64 b) {
    u64 d; asm("add.rn.f32x2 %0, %1, %2;" : "=l"(d) : "l"(a), "l"(b)); return d;
}
#define NEG1P 0xBF800000BF800000ULL   // (-1.f, -1.f)
#define TWOP  0x4000000040000000ULL   // ( 2.f,  2.f)

// 4-byte async copy global -> shared
__device__ __forceinline__ void cpa4(unsigned sdst, const float* gsrc) {
    asm volatile("cp.async.ca.shared.global [%0], [%1], 4;" :: "r"(sdst), "l"(gsrc));
}
#define CP_COMMIT() asm volatile("cp.async.commit_group;" ::: "memory")
#define CP_WAIT2()  asm volatile("cp.async.wait_group 2;" ::: "memory")

__device__ float g_partial[NBLOCKS];
__device__ unsigned int g_count = 0;
__device__ float g_zerosrc[8] = {0,0,0,0,0,0,0,0};

// minimax atan: odd poly on [0,1], reciprocal fold for |x|>1. max err ~2e-6 rad.
__device__ __forceinline__ float fast_atanf(float x)
{
    const float ax = fabsf(x);
    const bool inv = ax > 1.0f;
    const float t = inv ? __fdividef(1.0f, ax) : ax;
    const float z = t * t;
    float p = -0.0117212f;
    p = fmaf(p, z, 0.05265332f);
    p = fmaf(p, z, -0.11643287f);
    p = fmaf(p, z, 0.19354346f);
    p = fmaf(p, z, -0.33262347f);
    p = fmaf(p, z, 0.99997726f);
    p = p * t;
    const float r = inv ? (1.5707963267948966f - p) : p;
    return copysignf(r, x);
}

__global__ __launch_bounds__(NTHREADS, 2)
void demons_kernel(const float* __restrict__ Mp,
                   const float* __restrict__ Sp,
                   const float* __restrict__ Fp,
                   float* __restrict__ out)
{
    __shared__ u64 sm[NBUF][SMH][SMW];      // packed (M,S), 6-deep ring for cp.async
    __shared__ float warpred[NTHREADS / 32];
    __shared__ bool isLast;

    const int tx = threadIdx.x, ty = threadIdx.y;
    const int tid = ty * TX + tx;
    const int x = blockIdx.x * TX + tx;
    const int y = blockIdx.y * TY + ty;
    const int zbase = blockIdx.z * CZ;
    const int bid = blockIdx.x + GXD * (blockIdx.y + GYD * blockIdx.z);

    // halo mapping (z-invariant): each thread covers <=2 of 612 slots
    const int ly0 = tid / SMW, lx0 = tid - ly0 * SMW;
    const int gy0 = blockIdx.y * TY + ly0 - 1;
    const int gx0 = blockIdx.x * TX + lx0 - 1;
    const bool v0 = ((unsigned)gy0 < (unsigned)DH) && ((unsigned)gx0 < (unsigned)DW);
    const int off0 = v0 ? (gy0 * DW + gx0) : 0;

    const int i1 = tid + NTHREADS;
    const bool has1 = (i1 < CELLS);
    const int ly1 = i1 / SMW, lx1 = i1 - ly1 * SMW;
    const int gy1 = blockIdx.y * TY + ly1 - 1;
    const int gx1 = blockIdx.x * TX + lx1 - 1;
    const bool v1 = has1 && ((unsigned)gy1 < (unsigned)DH) && ((unsigned)gx1 < (unsigned)DW);
    const int off1 = v1 ? (gy1 * DW + gx1) : 0;

    const unsigned sbase = (unsigned)__cvta_generic_to_shared(&sm[0][0][0]);
    const unsigned a0 = sbase + (unsigned)(ly0 * SMW + lx0) * 8u;
    const unsigned a1 = sbase + (unsigned)(ly1 * SMW + lx1) * 8u;
    const float* gz = g_zerosrc;

    // incremental pointers; start at slice zbase-1
    const float* pM0 = Mp + (zbase - 1) * SLICE + off0;
    const float* pS0 = Sp + (zbase - 1) * SLICE + off0;
    const float* pM1 = Mp + (zbase - 1) * SLICE + off1;
    const float* pS1 = Sp + (zbase - 1) * SLICE + off1;

    // prologue: 3 groups, slices zbase-1..zbase+1 into buffers 0..2
    #pragma unroll
    for (int k = 0; k < 3; ++k) {
        const bool zin = (zbase - 1 + k >= 0);
        const unsigned ab0 = a0 + (unsigned)k * BUFBYTES;
        cpa4(ab0,      (v0 && zin) ? pM0 : gz);
        cpa4(ab0 + 4u, (v0 && zin) ? pS0 : gz);
        if (has1) {
            const unsigned ab1 = a1 + (unsigned)k * BUFBYTES;
            cpa4(ab1,      (v1 && zin) ? pM1 : gz);
            cpa4(ab1 + 4u, (v1 && zin) ? pS1 : gz);
        }
        CP_COMMIT();
        pM0 += SLICE; pS0 += SLICE; pM1 += SLICE; pS1 += SLICE;
    }

    // flow register pipeline, depth 2 (z in [zbase, zbase+CZ-1], guard-free)
    const float* pF = Fp + zbase * SLICE + y * DW + x;
    float Pfx = __ldg(pF), Pfy = __ldg(pF + NVOX), Pfz = __ldg(pF + 2 * NVOX);
    pF += SLICE;
    float Qfx = __ldg(pF), Qfy = __ldg(pF + NVOX), Qfz = __ldg(pF + 2 * NVOX);
    pF += SLICE;

    // packed per-slice responses, register ring of 3 (3 divides unroll 6 -> MOVs rename away)
    u64 A0, A1, A2, B0, B1, B2, C0, C1, C2, c1r, c2r;
    A0 = A1 = B0 = B1 = C0 = C1 = c1r = 0ULL;
    float acc = 0.f;

    #pragma unroll 6
    for (int j = 0; j <= CZ + 1; ++j) {          // 18 iterations = 3 unroll groups
        // group j (slice zbase-1+j) complete
        CP_WAIT2();
        __syncthreads();

        // issue prefetch for slice zbase+2+j into buffer (j+3)%6; always commit
        if (j <= CZ - 2) {
            const bool zin = (zbase + 2 + j < DD);
            const unsigned ab0 = a0 + (unsigned)((j + 3) % NBUF) * BUFBYTES;
            cpa4(ab0,      (v0 && zin) ? pM0 : gz);
            cpa4(ab0 + 4u, (v0 && zin) ? pS0 : gz);
            if (has1) {
                const unsigned ab1 = a1 + (unsigned)((j + 3) % NBUF) * BUFBYTES;
                cpa4(ab1,      (v1 && zin) ? pM1 : gz);
                cpa4(ab1 + 4u, (v1 && zin) ? pS1 : gz);
            }
            pM0 += SLICE; pS0 += SLICE; pM1 += SLICE; pS1 += SLICE;
        }
        CP_COMMIT();

        const int b = j % NBUF;

        // in-plane separable responses, packed over (M,S)
        const u64 a0v = sm[b][ty + 0][tx], a1v = sm[b][ty + 0][tx + 1], a2v = sm[b][ty + 0][tx + 2];
        const u64 q0  = sm[b][ty + 1][tx], q1  = sm[b][ty + 1][tx + 1], q2  = sm[b][ty + 1][tx + 2];
        const u64 e0  = sm[b][ty + 2][tx], e1v = sm[b][ty + 2][tx + 1], e2v = sm[b][ty + 2][tx + 2];

        const u64 t0 = add2(a0v, a2v);
        const u64 rD0 = fma2(a0v, NEG1P, a2v);
        const u64 rS0 = fma2(TWOP, a1v, t0);
        const u64 rB0 = add2(a1v, t0);

        const u64 t1 = add2(q0, q2);
        const u64 rD1 = fma2(q0, NEG1P, q2);
        const u64 rB1 = add2(q1, t1);

        const u64 t2 = add2(e0, e2v);
        const u64 rD2 = fma2(e0, NEG1P, e2v);
        const u64 rS2 = fma2(TWOP, e1v, t2);
        const u64 rB2 = add2(e1v, t2);

        A2 = fma2(TWOP, rD1, add2(rD0, rD2));   // smooth_y x diff_x
        B2 = fma2(rS0, NEG1P, rS2);             // diff_y x smooth_x
        C2 = fma2(TWOP, rB1, add2(rB0, rB2));   // smooth_y x box_x
        c2r = q1;                               // center pair (M,S)

        // emit output voxel z = zbase + j - 2 once three slices are live
        if (j >= 2) {
            const u64 Gx = add2(add2(A0, A1), A2);     // (Mx, Sx)
            const u64 Gy = add2(add2(B0, B1), B2);     // (My, Sy)
            const u64 Gz = fma2(C0, NEG1P, C2);        // (Mz, Sz)

            float Mcv, Scv; upk2(c1r, Mcv, Scv);
            const float Id  = Mcv - Scv;
            const float Id2 = fmaf(Id, Id, FEPS);

            const u64 d = fma2(Gx, Gx, fma2(Gy, Gy, fma2(Gz, Gz, pk2(Id2, Id2))));

            float dM, dS; upk2(d, dM, dS);
            float Mx, Sx; upk2(Gx, Mx, Sx);
            float My, Sy; upk2(Gy, My, Sy);
            float Mz, Sz; upk2(Gz, Mz, Sz);

            // Ux/(Uz+eps) == nx/nz: Id and 1/(dS*dM) cancel
            const float nx = fmaf(Sx, dM, Mx * dS);
            const float ny = fmaf(Sy, dM, My * dS);
            const float nz = fmaf(Sz, dM, Mz * dS);
            const float rz = __fdividef(1.f, nz);
            const float dxz = fast_atanf(nx * rz);
            const float dyz = fast_atanf(ny * rz);

            const float ifz = __fdividef(1.f, Pfz + FEPS);
            const float fxz = fast_atanf(Pfx * ifz);
            const float fyz = fast_atanf(Pfy * ifz);

            const float d1 = fxz - dxz;
            const float d2 = fyz - dyz;
            acc = fmaf(d1, d1, acc);
            acc = fmaf(d2, d2, acc);

            // rotate flow pipeline; load F for z = zbase+j (used at j+2)
            Pfx = Qfx; Pfy = Qfy; Pfz = Qfz;
            if (j <= CZ - 1) {
                Qfx = __ldg(pF);
                Qfy = __ldg(pF + NVOX);
                Qfz = __ldg(pF + 2 * NVOX);
                pF += SLICE;
            }
        }

        // ring shift (packed) — fully renamed away under unroll 6
        A0 = A1; A1 = A2;  B0 = B1; B1 = B2;
        C0 = C1; C1 = C2;  c1r = c2r;
    }

    // block reduction: warp shuffle + smem
    #pragma unroll
    for (int o = 16; o > 0; o >>= 1) acc += __shfl_xor_sync(0xffffffffu, acc, o);
    if ((tid & 31) == 0) warpred[tid >> 5] = acc;
    __syncthreads();
    if (tid == 0) {
        float v = 0.f;
        #pragma unroll
        for (int w = 0; w < NTHREADS / 32; ++w) v += warpred[w];
        g_partial[bid] = v;
        __threadfence();
        const unsigned int c = atomicAdd(&g_count, 1u);
        isLast = (c == (unsigned)(NBLOCKS - 1));
    }
    __syncthreads();

    // last block reduces partials, writes scalar, resets counter
    if (isLast) {
        float s = 0.f;
        for (int i = tid; i < NBLOCKS; i += NTHREADS) s += g_partial[i];
        #pragma unroll
        for (int o = 16; o > 0; o >>= 1) s += __shfl_xor_sync(0xffffffffu, s, o);
        if ((tid & 31) == 0) warpred[tid >> 5] = s;
        __syncthreads();
        if (tid == 0) {
            float t = 0.f;
            #pragma unroll
            for (int w = 0; w < NTHREADS / 32; ++w) t += warpred[w];
            out[0] = t / (float)NVOX;
            g_count = 0u;
        }
    }
}

extern "C" void kernel_launch(void* const* d_in, const int* in_sizes, int n_in,
                              void* d_out, int out_size)
{
    const float* Mp = (const float*)d_in[0];
    const float* Sp = (const float*)d_in[1];
    const float* Fp = (const float*)d_in[2];
    float* out = (float*)d_out;

    dim3 grid(GXD, GYD, GZD);   // (5, 12, 10) = 600 blocks
    dim3 block(TX, TY, 1);      // (32, 16) = 512 threads
    demons_kernel<<<grid, block>>>(Mp, Sp, Fp, out);
}

// round 12
// speedup vs baseline: 1.1000x; 1.1000x over previous
#include <cuda_runtime.h>
#include <math.h>

// dims: (1,1,D=160,H=192,W=160), x fastest
#define DW 160
#define DH 192
#define DD 160
#define SLICE (DH*DW)
#define NVOX (DD*SLICE)

#define TX 32
#define TY 8
#define CZ 16
#define SMW (TX+2)
#define SMH (TY+2)
#define NTHREADS (TX*TY)
#define GXD (DW/TX)   // 5
#define GYD (DH/TY)   // 24
#define GZD (DD/CZ)   // 10
#define NBLOCKS (GXD*GYD*GZD)   // 1200
#define FEPS 1e-10f

#define CELLS (SMH*SMW)          // 340
#define BUFBYTES (CELLS*8)       // one slice buffer
#define NSLICEBUF 8              // 4 double-buffers x 2 slices

typedef unsigned long long u64;

// packed (lo,hi) f32x2 helpers — FFMA2/FADD2 only reachable via PTX
__device__ __forceinline__ u64 pk2(float lo, float hi) {
    u64 r; asm("mov.b64 %0, {%1, %2};" : "=l"(r) : "f"(lo), "f"(hi)); return r;
}
__device__ __forceinline__ void upk2(u64 v, float& lo, float& hi) {
    asm("mov.b64 {%0, %1}, %2;" : "=f"(lo), "=f"(hi) : "l"(v));
}
__device__ __forceinline__ u64 fma2(u64 a, u64 b, u64 c) {
    u64 d; asm("fma.rn.f32x2 %0, %1, %2, %3;" : "=l"(d) : "l"(a), "l"(b), "l"(c)); return d;
}
__device__ __forceinline__ u64 add2(u64 a, u64 b) {
    u64 d; asm("add.rn.f32x2 %0, %1, %2;" : "=l"(d) : "l"(a), "l"(b)); return d;
}
#define NEG1P 0xBF800000BF800000ULL   // (-1.f, -1.f)
#define TWOP  0x4000000040000000ULL   // ( 2.f,  2.f)

// 4-byte async copy global -> shared
__device__ __forceinline__ void cpa4(unsigned sdst, const float* gsrc) {
    asm volatile("cp.async.ca.shared.global [%0], [%1], 4;" :: "r"(sdst), "l"(gsrc));
}
#define CP_COMMIT() asm volatile("cp.async.commit_group;" ::: "memory")
#define CP_WAIT2()  asm volatile("cp.async.wait_group 2;" ::: "memory")

__device__ float g_partial[NBLOCKS];
__device__ unsigned int g_count = 0;
__device__ float g_zerosrc[8] = {0,0,0,0,0,0,0,0};

// minimax atan: odd poly on [0,1], reciprocal fold for |x|>1. max err ~2e-6 rad.
__device__ __forceinline__ float fast_atanf(float x)
{
    const float ax = fabsf(x);
    const bool inv = ax > 1.0f;
    const float t = inv ? __fdividef(1.0f, ax) : ax;
    const float z = t * t;
    float p = -0.0117212f;
    p = fmaf(p, z, 0.05265332f);
    p = fmaf(p, z, -0.11643287f);
    p = fmaf(p, z, 0.19354346f);
    p = fmaf(p, z, -0.33262347f);
    p = fmaf(p, z, 0.99997726f);
    p = p * t;
    const float r = inv ? (1.5707963267948966f - p) : p;
    return copysignf(r, x);
}

__global__ __launch_bounds__(NTHREADS, 4)
void demons_kernel(const float* __restrict__ Mp,
                   const float* __restrict__ Sp,
                   const float* __restrict__ Fp,
                   float* __restrict__ out)
{
    __shared__ u64 sm[NSLICEBUF][SMH][SMW];   // packed (M,S); slice j -> buffer j%8
    __shared__ float warpred[NTHREADS / 32];
    __shared__ bool isLast;

    const int tx = threadIdx.x, ty = threadIdx.y;
    const int tid = ty * TX + tx;
    const int x = blockIdx.x * TX + tx;
    const int y = blockIdx.y * TY + ty;
    const int zbase = blockIdx.z * CZ;
    const int bid = blockIdx.x + GXD * (blockIdx.y + GYD * blockIdx.z);

    // halo mapping (z-invariant): each thread covers <=2 of 340 slots
    const int ly0 = tid / SMW, lx0 = tid - ly0 * SMW;
    const int gy0 = blockIdx.y * TY + ly0 - 1;
    const int gx0 = blockIdx.x * TX + lx0 - 1;
    const bool v0 = ((unsigned)gy0 < (unsigned)DH) && ((unsigned)gx0 < (unsigned)DW);
    const int off0 = v0 ? (gy0 * DW + gx0) : 0;

    const int i1 = tid + NTHREADS;
    const bool has1 = (i1 < CELLS);
    const int ly1 = i1 / SMW, lx1 = i1 - ly1 * SMW;
    const int gy1 = blockIdx.y * TY + ly1 - 1;
    const int gx1 = blockIdx.x * TX + lx1 - 1;
    const bool v1 = has1 && ((unsigned)gy1 < (unsigned)DH) && ((unsigned)gx1 < (unsigned)DW);
    const int off1 = v1 ? (gy1 * DW + gx1) : 0;

    const unsigned sbase = (unsigned)__cvta_generic_to_shared(&sm[0][0][0]);
    const unsigned a0 = sbase + (unsigned)(ly0 * SMW + lx0) * 8u;
    const unsigned a1 = sbase + (unsigned)(ly1 * SMW + lx1) * 8u;
    const float* gz = g_zerosrc;

    // incremental pointers; start at slice zbase-1 (slice index 0)
    const float* pM0 = Mp + (zbase - 1) * SLICE + off0;
    const float* pS0 = Sp + (zbase - 1) * SLICE + off0;
    const float* pM1 = Mp + (zbase - 1) * SLICE + off1;
    const float* pS1 = Sp + (zbase - 1) * SLICE + off1;

    // prologue: 3 dbuf groups = slices 0..5 (z = zbase-1 .. zbase+4; upper always < DD)
    #pragma unroll
    for (int k = 0; k < 6; ++k) {
        const bool zin = (zbase - 1 + k >= 0);
        const unsigned ab0 = a0 + (unsigned)k * BUFBYTES;
        cpa4(ab0,      (v0 && zin) ? pM0 : gz);
        cpa4(ab0 + 4u, (v0 && zin) ? pS0 : gz);
        if (has1) {
            const unsigned ab1 = a1 + (unsigned)k * BUFBYTES;
            cpa4(ab1,      (v1 && zin) ? pM1 : gz);
            cpa4(ab1 + 4u, (v1 && zin) ? pS1 : gz);
        }
        if (k & 1) CP_COMMIT();
        pM0 += SLICE; pS0 += SLICE; pM1 += SLICE; pS1 += SLICE;
    }

    // flow register pipeline, depth 2 (z in [zbase, zbase+CZ-1], guard-free)
    const float* pF = Fp + zbase * SLICE + y * DW + x;
    float Pfx = __ldg(pF), Pfy = __ldg(pF + NVOX), Pfz = __ldg(pF + 2 * NVOX);
    pF += SLICE;
    float Qfx = __ldg(pF), Qfy = __ldg(pF + NVOX), Qfz = __ldg(pF + 2 * NVOX);
    pF += SLICE;

    // packed per-slice responses, register ring of 3; advances 2/step -> period 3 steps
    u64 A0, A1, A2, B0, B1, B2, C0, C1, C2, c1r, c2r;
    A0 = A1 = B0 = B1 = C0 = C1 = c1r = 0ULL;
    float acc = 0.f;

// one slice: stencil responses from buffer BUF, emit for slice index J, ring shift
#define DO_SLICE(BUF, J) do {                                                                   \
    const u64 a0v = sm[BUF][ty + 0][tx], a1v = sm[BUF][ty + 0][tx + 1], a2v = sm[BUF][ty + 0][tx + 2]; \
    const u64 q0  = sm[BUF][ty + 1][tx], q1  = sm[BUF][ty + 1][tx + 1], q2  = sm[BUF][ty + 1][tx + 2]; \
    const u64 e0  = sm[BUF][ty + 2][tx], e1v = sm[BUF][ty + 2][tx + 1], e2v = sm[BUF][ty + 2][tx + 2]; \
    const u64 t0 = add2(a0v, a2v);                                                              \
    const u64 rD0 = fma2(a0v, NEG1P, a2v);                                                      \
    const u64 rS0 = fma2(TWOP, a1v, t0);                                                        \
    const u64 rB0 = add2(a1v, t0);                                                              \
    const u64 t1 = add2(q0, q2);                                                                \
    const u64 rD1 = fma2(q0, NEG1P, q2);                                                        \
    const u64 rB1 = add2(q1, t1);                                                               \
    const u64 t2 = add2(e0, e2v);                                                               \
    const u64 rD2 = fma2(e0, NEG1P, e2v);                                                       \
    const u64 rS2 = fma2(TWOP, e1v, t2);                                                        \
    const u64 rB2 = add2(e1v, t2);                                                              \
    A2 = fma2(TWOP, rD1, add2(rD0, rD2));                                                       \
    B2 = fma2(rS0, NEG1P, rS2);                                                                 \
    C2 = fma2(TWOP, rB1, add2(rB0, rB2));                                                       \
    c2r = q1;                                                                                   \
    if ((J) >= 2) {                                                                             \
        const u64 Gx = add2(add2(A0, A1), A2);                                                  \
        const u64 Gy = add2(add2(B0, B1), B2);                                                  \
        const u64 Gz = fma2(C0, NEG1P, C2);                                                     \
        float Mcv, Scv; upk2(c1r, Mcv, Scv);                                                    \
        const float Id  = Mcv - Scv;                                                            \
        const float Id2 = fmaf(Id, Id, FEPS);                                                   \
        const u64 d = fma2(Gx, Gx, fma2(Gy, Gy, fma2(Gz, Gz, pk2(Id2, Id2))));                  \
        float dM, dS; upk2(d, dM, dS);                                                          \
        float Mx, Sx; upk2(Gx, Mx, Sx);                                                         \
        float My, Sy; upk2(Gy, My, Sy);                                                         \
        float Mz, Sz; upk2(Gz, Mz, Sz);                                                         \
        const float nx = fmaf(Sx, dM, Mx * dS);                                                 \
        const float ny = fmaf(Sy, dM, My * dS);                                                 \
        const float nz = fmaf(Sz, dM, Mz * dS);                                                 \
        const float rz = __fdividef(1.f, nz);                                                   \
        const float dxz = fast_atanf(nx * rz);                                                  \
        const float dyz = fast_atanf(ny * rz);                                                  \
        const float ifz = __fdividef(1.f, Pfz + FEPS);                                          \
        const float fxz = fast_atanf(Pfx * ifz);                                                \
        const float fyz = fast_atanf(Pfy * ifz);                                                \
        const float d1 = fxz - dxz;                                                             \
        const float d2 = fyz - dyz;                                                             \
        acc = fmaf(d1, d1, acc);                                                                \
        acc = fmaf(d2, d2, acc);                                                                \
        Pfx = Qfx; Pfy = Qfy; Pfz = Qfz;                                                        \
        if ((J) <= CZ - 1) {                                                                    \
            Qfx = __ldg(pF);                                                                    \
            Qfy = __ldg(pF + NVOX);                                                             \
            Qfz = __ldg(pF + 2 * NVOX);                                                         \
            pF += SLICE;                                                                        \
        }                                                                                       \
    }                                                                                           \
    A0 = A1; A1 = A2;  B0 = B1; B1 = B2;                                                        \
    C0 = C1; C1 = C2;  c1r = c2r;                                                               \
} while (0)

    #pragma unroll 3
    for (int s = 0; s < 9; ++s) {               // 9 steps x 2 slices = 18 slices
        // dbuf group s complete (wait own copies, then make all visible)
        CP_WAIT2();
        __syncthreads();

        // prefetch dbuf (s+3)&3 = slices 2s+6, 2s+7 (z = zbase+2s+5, +6)
        if (s <= 5) {
            const unsigned ab = a0 + (unsigned)(((s + 3) & 3) * 2) * BUFBYTES;
            const bool zin0 = (zbase + 2 * s + 5 < DD);
            const bool zin1 = (zbase + 2 * s + 6 < DD);
            cpa4(ab,                 (v0 && zin0) ? pM0 : gz);
            cpa4(ab + 4u,            (v0 && zin0) ? pS0 : gz);
            cpa4(ab + BUFBYTES,      (v0 && zin1) ? (pM0 + SLICE) : gz);
            cpa4(ab + BUFBYTES + 4u, (v0 && zin1) ? (pS0 + SLICE) : gz);
            if (has1) {
                const unsigned ab1 = a1 + (unsigned)(((s + 3) & 3) * 2) * BUFBYTES;
                cpa4(ab1,                 (v1 && zin0) ? pM1 : gz);
                cpa4(ab1 + 4u,            (v1 && zin0) ? pS1 : gz);
                cpa4(ab1 + BUFBYTES,      (v1 && zin1) ? (pM1 + SLICE) : gz);
                cpa4(ab1 + BUFBYTES + 4u, (v1 && zin1) ? (pS1 + SLICE) : gz);
            }
            pM0 += 2 * SLICE; pS0 += 2 * SLICE; pM1 += 2 * SLICE; pS1 += 2 * SLICE;
        }
        CP_COMMIT();

        const int db = (s & 3) * 2;             // slice buffers db, db+1
        DO_SLICE(db,     2 * s);
        DO_SLICE(db + 1, 2 * s + 1);
    }
#undef DO_SLICE

    // block reduction: warp shuffle + smem
    #pragma unroll
    for (int o = 16; o > 0; o >>= 1) acc += __shfl_xor_sync(0xffffffffu, acc, o);
    if ((tid & 31) == 0) warpred[tid >> 5] = acc;
    __syncthreads();
    if (tid == 0) {
        float v = 0.f;
        #pragma unroll
        for (int w = 0; w < NTHREADS / 32; ++w) v += warpred[w];
        g_partial[bid] = v;
        __threadfence();
        const unsigned int c = atomicAdd(&g_count, 1u);
        isLast = (c == (unsigned)(NBLOCKS - 1));
    }
    __syncthreads();

    // last block reduces partials, writes scalar, resets counter
    if (isLast) {
        float s = 0.f;
        for (int i = tid; i < NBLOCKS; i += NTHREADS) s += g_partial[i];
        #pragma unroll
        for (int o = 16; o > 0; o >>= 1) s += __shfl_xor_sync(0xffffffffu, s, o);
        if ((tid & 31) == 0) warpred[tid >> 5] = s;
        __syncthreads();
        if (tid == 0) {
            float t = 0.f;
            #pragma unroll
            for (int w = 0; w < NTHREADS / 32; ++w) t += warpred[w];
            out[0] = t / (float)NVOX;
            g_count = 0u;
        }
    }
}

extern "C" void kernel_launch(void* const* d_in, const int* in_sizes, int n_in,
                              void* d_out, int out_size)
{
    const float* Mp = (const float*)d_in[0];
    const float* Sp = (const float*)d_in[1];
    const float* Fp = (const float*)d_in[2];
    float* out = (float*)d_out;

    dim3 grid(GXD, GYD, GZD);   // (5, 24, 10) = 1200 blocks
    dim3 block(TX, TY, 1);      // (32, 8)
    demons_kernel<<<grid, block>>>(Mp, Sp, Fp, out);
}

// round 13
// speedup vs baseline: 1.1472x; 1.0429x over previous
#include <cuda_runtime.h>
#include <math.h>

// dims: (1,1,D=160,H=192,W=160), x fastest
#define DW 160
#define DH 192
#define DD 160
#define SLICE (DH*DW)
#define NVOX (DD*SLICE)

#define TX 32
#define TY 8
#define CZ 16
#define SMW (TX+2)
#define SMH (TY+2)
#define NTHREADS (TX*TY)
#define GXD (DW/TX)   // 5
#define GYD (DH/TY)   // 24
#define GZD (DD/CZ)   // 10
#define NBLOCKS (GXD*GYD*GZD)   // 1200
#define FEPS 1e-10f

#define CELLS (SMH*SMW)          // 340
#define BUFBYTES (CELLS*8)       // one slice buffer
#define NSLICEBUF 8              // 4 double-buffers x 2 slices

typedef unsigned long long u64;

// packed (lo,hi) f32x2 helpers — FFMA2/FADD2 only reachable via PTX
__device__ __forceinline__ u64 pk2(float lo, float hi) {
    u64 r; asm("mov.b64 %0, {%1, %2};" : "=l"(r) : "f"(lo), "f"(hi)); return r;
}
__device__ __forceinline__ void upk2(u64 v, float& lo, float& hi) {
    asm("mov.b64 {%0, %1}, %2;" : "=f"(lo), "=f"(hi) : "l"(v));
}
__device__ __forceinline__ u64 fma2(u64 a, u64 b, u64 c) {
    u64 d; asm("fma.rn.f32x2 %0, %1, %2, %3;" : "=l"(d) : "l"(a), "l"(b), "l"(c)); return d;
}
__device__ __forceinline__ u64 add2(u64 a, u64 b) {
    u64 d; asm("add.rn.f32x2 %0, %1, %2;" : "=l"(d) : "l"(a), "l"(b)); return d;
}
#define NEG1P 0xBF800000BF800000ULL   // (-1.f, -1.f)
#define TWOP  0x4000000040000000ULL   // ( 2.f,  2.f)

// 4-byte async copy global -> shared
__device__ __forceinline__ void cpa4(unsigned sdst, const float* gsrc) {
    asm volatile("cp.async.ca.shared.global [%0], [%1], 4;" :: "r"(sdst), "l"(gsrc));
}
#define CP_COMMIT() asm volatile("cp.async.commit_group;" ::: "memory")
#define CP_WAIT2()  asm volatile("cp.async.wait_group 2;" ::: "memory")

__device__ float g_partial[NBLOCKS];
__device__ unsigned int g_count = 0;
__device__ float g_zerosrc[8] = {0,0,0,0,0,0,0,0};

// minimax atan deg-7: odd poly on [0,1], reciprocal fold for |x|>1. max err ~1e-4 rad.
__device__ __forceinline__ float fast_atanf(float x)
{
    const float ax = fabsf(x);
    const bool inv = ax > 1.0f;
    const float t = inv ? __fdividef(1.0f, ax) : ax;
    const float z = t * t;
    float p = -0.0389929f;
    p = fmaf(p, z, 0.1462766f);
    p = fmaf(p, z, -0.3211819f);
    p = fmaf(p, z, 0.9992150f);
    p = p * t;
    const float r = inv ? (1.5707963f - p) : p;
    return copysignf(r, x);
}

__global__ __launch_bounds__(NTHREADS, 4)
void demons_kernel(const float* __restrict__ Mp,
                   const float* __restrict__ Sp,
                   const float* __restrict__ Fp,
                   float* __restrict__ out)
{
    __shared__ u64 sm[NSLICEBUF][SMH][SMW];   // packed (M,S); slice j -> buffer j%8
    __shared__ float warpred[NTHREADS / 32];
    __shared__ bool isLast;

    const int tx = threadIdx.x, ty = threadIdx.y;
    const int tid = ty * TX + tx;
    const int x = blockIdx.x * TX + tx;
    const int y = blockIdx.y * TY + ty;
    const int zbase = blockIdx.z * CZ;
    const int bid = blockIdx.x + GXD * (blockIdx.y + GYD * blockIdx.z);

    // halo mapping (z-invariant): each thread covers <=2 of 340 slots
    const int ly0 = tid / SMW, lx0 = tid - ly0 * SMW;
    const int gy0 = blockIdx.y * TY + ly0 - 1;
    const int gx0 = blockIdx.x * TX + lx0 - 1;
    const bool v0 = ((unsigned)gy0 < (unsigned)DH) && ((unsigned)gx0 < (unsigned)DW);
    const int off0 = v0 ? (gy0 * DW + gx0) : 0;

    const int i1 = tid + NTHREADS;
    const bool has1 = (i1 < CELLS);
    const int ly1 = i1 / SMW, lx1 = i1 - ly1 * SMW;
    const int gy1 = blockIdx.y * TY + ly1 - 1;
    const int gx1 = blockIdx.x * TX + lx1 - 1;
    const bool v1 = has1 && ((unsigned)gy1 < (unsigned)DH) && ((unsigned)gx1 < (unsigned)DW);
    const int off1 = v1 ? (gy1 * DW + gx1) : 0;

    const unsigned sbase = (unsigned)__cvta_generic_to_shared(&sm[0][0][0]);
    const unsigned a0 = sbase + (unsigned)(ly0 * SMW + lx0) * 8u;
    const unsigned a1 = sbase + (unsigned)(ly1 * SMW + lx1) * 8u;
    const float* gz = g_zerosrc;

    // incremental pointers; start at slice zbase-1 (slice index 0)
    const float* pM0 = Mp + (zbase - 1) * SLICE + off0;
    const float* pS0 = Sp + (zbase - 1) * SLICE + off0;
    const float* pM1 = Mp + (zbase - 1) * SLICE + off1;
    const float* pS1 = Sp + (zbase - 1) * SLICE + off1;

    // prologue: 3 dbuf groups = slices 0..5 (z = zbase-1 .. zbase+4; upper always < DD)
    #pragma unroll
    for (int k = 0; k < 6; ++k) {
        const bool zin = (zbase - 1 + k >= 0);
        const unsigned ab0 = a0 + (unsigned)k * BUFBYTES;
        cpa4(ab0,      (v0 && zin) ? pM0 : gz);
        cpa4(ab0 + 4u, (v0 && zin) ? pS0 : gz);
        if (has1) {
            const unsigned ab1 = a1 + (unsigned)k * BUFBYTES;
            cpa4(ab1,      (v1 && zin) ? pM1 : gz);
            cpa4(ab1 + 4u, (v1 && zin) ? pS1 : gz);
        }
        if (k & 1) CP_COMMIT();
        pM0 += SLICE; pS0 += SLICE; pM1 += SLICE; pS1 += SLICE;
    }

    // flow registers: F0 serves even emit slices, F1 odd — no rotation MOVs.
    // F0 preloaded z=zbase (emit J=2), F1 z=zbase+1 (emit J=3); each reloads its
    // own next value (z+2) right after use. z stays in [zbase, zbase+CZ-1]: guard-free.
    const float* pF0 = Fp + zbase * SLICE + y * DW + x;
    const float* pF1 = pF0 + SLICE;
    float F0x = __ldg(pF0), F0y = __ldg(pF0 + NVOX), F0z = __ldg(pF0 + 2 * NVOX);
    pF0 += 2 * SLICE;
    float F1x = __ldg(pF1), F1y = __ldg(pF1 + NVOX), F1z = __ldg(pF1 + 2 * NVOX);
    pF1 += 2 * SLICE;

    // packed per-slice responses, register ring of 3; advances 2/step -> period 3 steps
    u64 A0, A1, A2, B0, B1, B2, C0, C1, C2, c1r, c2r;
    A0 = A1 = B0 = B1 = C0 = C1 = c1r = 0ULL;
    float acc = 0.f;

// one slice: stencil responses from buffer BUF, emit for slice index J using flow
// registers FX/FY/FZ with reload pointer PFP, ring shift
#define DO_SLICE(BUF, J, FX, FY, FZ, PFP) do {                                                  \
    const u64 a0v = sm[BUF][ty + 0][tx], a1v = sm[BUF][ty + 0][tx + 1], a2v = sm[BUF][ty + 0][tx + 2]; \
    const u64 q0  = sm[BUF][ty + 1][tx], q1  = sm[BUF][ty + 1][tx + 1], q2  = sm[BUF][ty + 1][tx + 2]; \
    const u64 e0  = sm[BUF][ty + 2][tx], e1v = sm[BUF][ty + 2][tx + 1], e2v = sm[BUF][ty + 2][tx + 2]; \
    const u64 t0 = add2(a0v, a2v);                                                              \
    const u64 rD0 = fma2(a0v, NEG1P, a2v);                                                      \
    const u64 rS0 = fma2(TWOP, a1v, t0);                                                        \
    const u64 rB0 = add2(a1v, t0);                                                              \
    const u64 t1 = add2(q0, q2);                                                                \
    const u64 rD1 = fma2(q0, NEG1P, q2);                                                        \
    const u64 rB1 = add2(q1, t1);                                                               \
    const u64 t2 = add2(e0, e2v);                                                               \
    const u64 rD2 = fma2(e0, NEG1P, e2v);                                                       \
    const u64 rS2 = fma2(TWOP, e1v, t2);                                                        \
    const u64 rB2 = add2(e1v, t2);                                                              \
    A2 = fma2(TWOP, rD1, add2(rD0, rD2));                                                       \
    B2 = fma2(rS0, NEG1P, rS2);                                                                 \
    C2 = fma2(TWOP, rB1, add2(rB0, rB2));                                                       \
    c2r = q1;                                                                                   \
    if ((J) >= 2) {                                                                             \
        const u64 Gx = add2(add2(A0, A1), A2);                                                  \
        const u64 Gy = add2(add2(B0, B1), B2);                                                  \
        const u64 Gz = fma2(C0, NEG1P, C2);                                                     \
        float Mcv, Scv; upk2(c1r, Mcv, Scv);                                                    \
        const float Id  = Mcv - Scv;                                                            \
        const float Id2 = fmaf(Id, Id, FEPS);                                                   \
        const u64 d = fma2(Gx, Gx, fma2(Gy, Gy, fma2(Gz, Gz, pk2(Id2, Id2))));                  \
        float dM, dS; upk2(d, dM, dS);                                                          \
        float Mx, Sx; upk2(Gx, Mx, Sx);                                                         \
        float My, Sy; upk2(Gy, My, Sy);                                                         \
        float Mz, Sz; upk2(Gz, Mz, Sz);                                                         \
        const float nx = fmaf(Sx, dM, Mx * dS);                                                 \
        const float ny = fmaf(Sy, dM, My * dS);                                                 \
        const float nz = fmaf(Sz, dM, Mz * dS);                                                 \
        const float rz = __fdividef(1.f, nz);                                                   \
        const float dxz = fast_atanf(nx * rz);                                                  \
        const float dyz = fast_atanf(ny * rz);                                                  \
        const float ifz = __fdividef(1.f, FZ + FEPS);                                           \
        const float fxz = fast_atanf(FX * ifz);                                                 \
        const float fyz = fast_atanf(FY * ifz);                                                 \
        const float d1 = fxz - dxz;                                                             \
        const float d2 = fyz - dyz;                                                             \
        acc = fmaf(d1, d1, acc);                                                                \
        acc = fmaf(d2, d2, acc);                                                                \
        if ((J) <= CZ - 1) {                                                                    \
            FX = __ldg(PFP);                                                                    \
            FY = __ldg(PFP + NVOX);                                                             \
            FZ = __ldg(PFP + 2 * NVOX);                                                         \
            PFP += 2 * SLICE;                                                                   \
        }                                                                                       \
    }                                                                                           \
    A0 = A1; A1 = A2;  B0 = B1; B1 = B2;                                                        \
    C0 = C1; C1 = C2;  c1r = c2r;                                                               \
} while (0)

    #pragma unroll 3
    for (int s = 0; s < 9; ++s) {               // 9 steps x 2 slices = 18 slices
        // dbuf group s complete (wait own copies, then make all visible)
        CP_WAIT2();
        __syncthreads();

        // prefetch dbuf (s+3)&3 = slices 2s+6, 2s+7 (z = zbase+2s+5, +6)
        if (s <= 5) {
            const unsigned ab = a0 + (unsigned)(((s + 3) & 3) * 2) * BUFBYTES;
            const bool zin0 = (zbase + 2 * s + 5 < DD);
            const bool zin1 = (zbase + 2 * s + 6 < DD);
            cpa4(ab,                 (v0 && zin0) ? pM0 : gz);
            cpa4(ab + 4u,            (v0 && zin0) ? pS0 : gz);
            cpa4(ab + BUFBYTES,      (v0 && zin1) ? (pM0 + SLICE) : gz);
            cpa4(ab + BUFBYTES + 4u, (v0 && zin1) ? (pS0 + SLICE) : gz);
            if (has1) {
                const unsigned ab1 = a1 + (unsigned)(((s + 3) & 3) * 2) * BUFBYTES;
                cpa4(ab1,                 (v1 && zin0) ? pM1 : gz);
                cpa4(ab1 + 4u,            (v1 && zin0) ? pS1 : gz);
                cpa4(ab1 + BUFBYTES,      (v1 && zin1) ? (pM1 + SLICE) : gz);
                cpa4(ab1 + BUFBYTES + 4u, (v1 && zin1) ? (pS1 + SLICE) : gz);
            }
            pM0 += 2 * SLICE; pS0 += 2 * SLICE; pM1 += 2 * SLICE; pS1 += 2 * SLICE;
        }
        CP_COMMIT();

        const int db = (s & 3) * 2;             // slice buffers db, db+1
        DO_SLICE(db,     2 * s,     F0x, F0y, F0z, pF0);
        DO_SLICE(db + 1, 2 * s + 1, F1x, F1y, F1z, pF1);
    }
#undef DO_SLICE

    // block reduction: warp shuffle + smem
    #pragma unroll
    for (int o = 16; o > 0; o >>= 1) acc += __shfl_xor_sync(0xffffffffu, acc, o);
    if ((tid & 31) == 0) warpred[tid >> 5] = acc;
    __syncthreads();
    if (tid == 0) {
        float v = 0.f;
        #pragma unroll
        for (int w = 0; w < NTHREADS / 32; ++w) v += warpred[w];
        g_partial[bid] = v;
        __threadfence();
        const unsigned int c = atomicAdd(&g_count, 1u);
        isLast = (c == (unsigned)(NBLOCKS - 1));
    }
    __syncthreads();

    // last block reduces partials, writes scalar, resets counter
    if (isLast) {
        float s = 0.f;
        for (int i = tid; i < NBLOCKS; i += NTHREADS) s += g_partial[i];
        #pragma unroll
        for (int o = 16; o > 0; o >>= 1) s += __shfl_xor_sync(0xffffffffu, s, o);
        if ((tid & 31) == 0) warpred[tid >> 5] = s;
        __syncthreads();
        if (tid == 0) {
            float t = 0.f;
            #pragma unroll
            for (int w = 0; w < NTHREADS / 32; ++w) t += warpred[w];
            out[0] = t / (float)NVOX;
            g_count = 0u;
        }
    }
}

extern "C" void kernel_launch(void* const* d_in, const int* in_sizes, int n_in,
                              void* d_out, int out_size)
{
    const float* Mp = (const float*)d_in[0];
    const float* Sp = (const float*)d_in[1];
    const float* Fp = (const float*)d_in[2];
    float* out = (float*)d_out;

    dim3 grid(GXD, GYD, GZD);   // (5, 24, 10) = 1200 blocks
    dim3 block(TX, TY, 1);      // (32, 8)
    demons_kernel<<<grid, block>>>(Mp, Sp, Fp, out);
}

// round 14
// speedup vs baseline: 1.1543x; 1.0062x over previous
#include <cuda_runtime.h>
#include <math.h>

// dims: (1,1,D=160,H=192,W=160), x fastest
#define DW 160
#define DH 192
#define DD 160
#define SLICE (DH*DW)
#define NVOX (DD*SLICE)

#define TX 32
#define TY 8
#define CZ 16
#define SMW (TX+2)
#define SMH (TY+2)
#define NTHREADS (TX*TY)
#define GXD (DW/TX)   // 5
#define GYD (DH/TY)   // 24
#define GZD (DD/CZ)   // 10
#define NBLOCKS (GXD*GYD*GZD)   // 1200
#define FEPS 1e-10f
#define FPI  3.14159265358979f

#define CELLS (SMH*SMW)          // 340
#define BUFBYTES (CELLS*8)       // one slice buffer
#define NSLICEBUF 8              // 4 double-buffers x 2 slices

typedef unsigned long long u64;

// packed (lo,hi) f32x2 helpers — FFMA2/FADD2 only reachable via PTX
__device__ __forceinline__ u64 pk2(float lo, float hi) {
    u64 r; asm("mov.b64 %0, {%1, %2};" : "=l"(r) : "f"(lo), "f"(hi)); return r;
}
__device__ __forceinline__ void upk2(u64 v, float& lo, float& hi) {
    asm("mov.b64 {%0, %1}, %2;" : "=f"(lo), "=f"(hi) : "l"(v));
}
__device__ __forceinline__ u64 fma2(u64 a, u64 b, u64 c) {
    u64 d; asm("fma.rn.f32x2 %0, %1, %2, %3;" : "=l"(d) : "l"(a), "l"(b), "l"(c)); return d;
}
__device__ __forceinline__ u64 add2(u64 a, u64 b) {
    u64 d; asm("add.rn.f32x2 %0, %1, %2;" : "=l"(d) : "l"(a), "l"(b)); return d;
}
#define NEG1P 0xBF800000BF800000ULL   // (-1.f, -1.f)
#define TWOP  0x4000000040000000ULL   // ( 2.f,  2.f)

// 4-byte async copy global -> shared
__device__ __forceinline__ void cpa4(unsigned sdst, const float* gsrc) {
    asm volatile("cp.async.ca.shared.global [%0], [%1], 4;" :: "r"(sdst), "l"(gsrc));
}
#define CP_COMMIT() asm volatile("cp.async.commit_group;" ::: "memory")
#define CP_WAIT2()  asm volatile("cp.async.wait_group 2;" ::: "memory")

__device__ float g_partial[NBLOCKS];
__device__ unsigned int g_count = 0;
__device__ float g_zerosrc[8] = {0,0,0,0,0,0,0,0};

// minimax atan deg-7: odd poly on [0,1], reciprocal fold for |x|>1. max err ~1e-4 rad.
__device__ __forceinline__ float fast_atanf(float x)
{
    const float ax = fabsf(x);
    const bool inv = ax > 1.0f;
    const float t = inv ? __fdividef(1.0f, ax) : ax;
    const float z = t * t;
    float p = -0.0389929f;
    p = fmaf(p, z, 0.1462766f);
    p = fmaf(p, z, -0.3211819f);
    p = fmaf(p, z, 0.9992150f);
    p = p * t;
    const float r = inv ? (1.5707963f - p) : p;
    return copysignf(r, x);
}

// e = atan(fa/fb) - atan(na/nb), exact quadrant handling.
// u = (fa*nb - na*fb)/(fb*nb + fa*na); correction +/-pi when 1+ab < 0.
__device__ __forceinline__ float atan_diff(float fa, float fb, float na, float nb, float w)
{
    // w = fb*nb passed in (shared across the two calls)
    const float num = fmaf(fa, nb, -na * fb);
    const float den = fmaf(fa, na, w);
    float e = fast_atanf(__fdividef(num, den));
    const float c = (den * w < 0.f) ? copysignf(FPI, num * w) : 0.f;
    return e + c;
}

__global__ __launch_bounds__(NTHREADS, 4)
void demons_kernel(const float* __restrict__ Mp,
                   const float* __restrict__ Sp,
                   const float* __restrict__ Fp,
                   float* __restrict__ out)
{
    __shared__ u64 sm[NSLICEBUF][SMH][SMW];   // packed (M,S); slice j -> buffer j%8
    __shared__ float warpred[NTHREADS / 32];
    __shared__ bool isLast;

    const int tx = threadIdx.x, ty = threadIdx.y;
    const int tid = ty * TX + tx;
    const int x = blockIdx.x * TX + tx;
    const int y = blockIdx.y * TY + ty;
    const int zbase = blockIdx.z * CZ;
    const int bid = blockIdx.x + GXD * (blockIdx.y + GYD * blockIdx.z);

    // halo mapping (z-invariant): each thread covers <=2 of 340 slots
    const int ly0 = tid / SMW, lx0 = tid - ly0 * SMW;
    const int gy0 = blockIdx.y * TY + ly0 - 1;
    const int gx0 = blockIdx.x * TX + lx0 - 1;
    const bool v0 = ((unsigned)gy0 < (unsigned)DH) && ((unsigned)gx0 < (unsigned)DW);
    const int off0 = v0 ? (gy0 * DW + gx0) : 0;

    const int i1 = tid + NTHREADS;
    const bool has1 = (i1 < CELLS);
    const int ly1 = i1 / SMW, lx1 = i1 - ly1 * SMW;
    const int gy1 = blockIdx.y * TY + ly1 - 1;
    const int gx1 = blockIdx.x * TX + lx1 - 1;
    const bool v1 = has1 && ((unsigned)gy1 < (unsigned)DH) && ((unsigned)gx1 < (unsigned)DW);
    const int off1 = v1 ? (gy1 * DW + gx1) : 0;

    const unsigned sbase = (unsigned)__cvta_generic_to_shared(&sm[0][0][0]);
    const unsigned a0 = sbase + (unsigned)(ly0 * SMW + lx0) * 8u;
    const unsigned a1 = sbase + (unsigned)(ly1 * SMW + lx1) * 8u;
    const float* gz = g_zerosrc;

    // incremental pointers; start at slice zbase-1 (slice index 0)
    const float* pM0 = Mp + (zbase - 1) * SLICE + off0;
    const float* pS0 = Sp + (zbase - 1) * SLICE + off0;
    const float* pM1 = Mp + (zbase - 1) * SLICE + off1;
    const float* pS1 = Sp + (zbase - 1) * SLICE + off1;

    // prologue: 3 dbuf groups = slices 0..5 (z = zbase-1 .. zbase+4; upper always < DD)
    #pragma unroll
    for (int k = 0; k < 6; ++k) {
        const bool zin = (zbase - 1 + k >= 0);
        const unsigned ab0 = a0 + (unsigned)k * BUFBYTES;
        cpa4(ab0,      (v0 && zin) ? pM0 : gz);
        cpa4(ab0 + 4u, (v0 && zin) ? pS0 : gz);
        if (has1) {
            const unsigned ab1 = a1 + (unsigned)k * BUFBYTES;
            cpa4(ab1,      (v1 && zin) ? pM1 : gz);
            cpa4(ab1 + 4u, (v1 && zin) ? pS1 : gz);
        }
        if (k & 1) CP_COMMIT();
        pM0 += SLICE; pS0 += SLICE; pM1 += SLICE; pS1 += SLICE;
    }

    // flow registers: F0 serves even emit slices, F1 odd — no rotation MOVs.
    const float* pF0 = Fp + zbase * SLICE + y * DW + x;
    const float* pF1 = pF0 + SLICE;
    float F0x = __ldg(pF0), F0y = __ldg(pF0 + NVOX), F0z = __ldg(pF0 + 2 * NVOX);
    pF0 += 2 * SLICE;
    float F1x = __ldg(pF1), F1y = __ldg(pF1 + NVOX), F1z = __ldg(pF1 + 2 * NVOX);
    pF1 += 2 * SLICE;

    // packed per-slice responses, register ring of 3; advances 2/step -> period 3 steps
    u64 A0, A1, A2, B0, B1, B2, C0, C1, C2, c1r, c2r;
    A0 = A1 = B0 = B1 = C0 = C1 = c1r = 0ULL;
    float acc = 0.f;

// one slice: stencil responses from buffer BUF, emit for slice index J using flow
// registers FX/FY/FZ with reload pointer PFP, ring shift
#define DO_SLICE(BUF, J, FX, FY, FZ, PFP) do {                                                  \
    const u64 a0v = sm[BUF][ty + 0][tx], a1v = sm[BUF][ty + 0][tx + 1], a2v = sm[BUF][ty + 0][tx + 2]; \
    const u64 q0  = sm[BUF][ty + 1][tx], q1  = sm[BUF][ty + 1][tx + 1], q2  = sm[BUF][ty + 1][tx + 2]; \
    const u64 e0  = sm[BUF][ty + 2][tx], e1v = sm[BUF][ty + 2][tx + 1], e2v = sm[BUF][ty + 2][tx + 2]; \
    const u64 t0 = add2(a0v, a2v);                                                              \
    const u64 rD0 = fma2(a0v, NEG1P, a2v);                                                      \
    const u64 rS0 = fma2(TWOP, a1v, t0);                                                        \
    const u64 rB0 = add2(a1v, t0);                                                              \
    const u64 t1 = add2(q0, q2);                                                                \
    const u64 rD1 = fma2(q0, NEG1P, q2);                                                        \
    const u64 rB1 = add2(q1, t1);                                                               \
    const u64 t2 = add2(e0, e2v);                                                               \
    const u64 rD2 = fma2(e0, NEG1P, e2v);                                                       \
    const u64 rS2 = fma2(TWOP, e1v, t2);                                                        \
    const u64 rB2 = add2(e1v, t2);                                                              \
    A2 = fma2(TWOP, rD1, add2(rD0, rD2));                                                       \
    B2 = fma2(rS0, NEG1P, rS2);                                                                 \
    C2 = fma2(TWOP, rB1, add2(rB0, rB2));                                                       \
    c2r = q1;                                                                                   \
    if ((J) >= 2) {                                                                             \
        const u64 Gx = add2(add2(A0, A1), A2);                                                  \
        const u64 Gy = add2(add2(B0, B1), B2);                                                  \
        const u64 Gz = fma2(C0, NEG1P, C2);                                                     \
        float Mcv, Scv; upk2(c1r, Mcv, Scv);                                                    \
        const float Id  = Mcv - Scv;                                                            \
        const float Id2 = fmaf(Id, Id, FEPS);                                                   \
        const u64 d = fma2(Gx, Gx, fma2(Gy, Gy, fma2(Gz, Gz, pk2(Id2, Id2))));                  \
        float dM, dS; upk2(d, dM, dS);                                                          \
        float Mx, Sx; upk2(Gx, Mx, Sx);                                                         \
        float My, Sy; upk2(Gy, My, Sy);                                                         \
        float Mz, Sz; upk2(Gz, Mz, Sz);                                                         \
        const float nx = fmaf(Sx, dM, Mx * dS);                                                 \
        const float ny = fmaf(Sy, dM, My * dS);                                                 \
        const float nz = fmaf(Sz, dM, Mz * dS);                                                 \
        const float FZe = FZ + FEPS;                                                            \
        const float w = FZe * nz;                                                               \
        const float d1 = atan_diff(FX, FZe, nx, nz, w);                                         \
        const float d2 = atan_diff(FY, FZe, ny, nz, w);                                         \
        acc = fmaf(d1, d1, acc);                                                                \
        acc = fmaf(d2, d2, acc);                                                                \
        if ((J) <= CZ - 1) {                                                                    \
            FX = __ldg(PFP);                                                                    \
            FY = __ldg(PFP + NVOX);                                                             \
            FZ = __ldg(PFP + 2 * NVOX);                                                         \
            PFP += 2 * SLICE;                                                                   \
        }                                                                                       \
    }                                                                                           \
    A0 = A1; A1 = A2;  B0 = B1; B1 = B2;                                                        \
    C0 = C1; C1 = C2;  c1r = c2r;                                                               \
} while (0)

    #pragma unroll 3
    for (int s = 0; s < 9; ++s) {               // 9 steps x 2 slices = 18 slices
        // dbuf group s complete (wait own copies, then make all visible)
        CP_WAIT2();
        __syncthreads();

        // prefetch dbuf (s+3)&3 = slices 2s+6, 2s+7 (z = zbase+2s+5, +6)
        if (s <= 5) {
            const unsigned ab = a0 + (unsigned)(((s + 3) & 3) * 2) * BUFBYTES;
            const bool zin0 = (zbase + 2 * s + 5 < DD);
            const bool zin1 = (zbase + 2 * s + 6 < DD);
            cpa4(ab,                 (v0 && zin0) ? pM0 : gz);
            cpa4(ab + 4u,            (v0 && zin0) ? pS0 : gz);
            cpa4(ab + BUFBYTES,      (v0 && zin1) ? (pM0 + SLICE) : gz);
            cpa4(ab + BUFBYTES + 4u, (v0 && zin1) ? (pS0 + SLICE) : gz);
            if (has1) {
                const unsigned ab1 = a1 + (unsigned)(((s + 3) & 3) * 2) * BUFBYTES;
                cpa4(ab1,                 (v1 && zin0) ? pM1 : gz);
                cpa4(ab1 + 4u,            (v1 && zin0) ? pS1 : gz);
                cpa4(ab1 + BUFBYTES,      (v1 && zin1) ? (pM1 + SLICE) : gz);
                cpa4(ab1 + BUFBYTES + 4u, (v1 && zin1) ? (pS1 + SLICE) : gz);
            }
            pM0 += 2 * SLICE; pS0 += 2 * SLICE; pM1 += 2 * SLICE; pS1 += 2 * SLICE;
        }
        CP_COMMIT();

        const int db = (s & 3) * 2;             // slice buffers db, db+1
        DO_SLICE(db,     2 * s,     F0x, F0y, F0z, pF0);
        DO_SLICE(db + 1, 2 * s + 1, F1x, F1y, F1z, pF1);
    }
#undef DO_SLICE

    // block reduction: warp shuffle + smem
    #pragma unroll
    for (int o = 16; o > 0; o >>= 1) acc += __shfl_xor_sync(0xffffffffu, acc, o);
    if ((tid & 31) == 0) warpred[tid >> 5] = acc;
    __syncthreads();
    if (tid == 0) {
        float v = 0.f;
        #pragma unroll
        for (int w = 0; w < NTHREADS / 32; ++w) v += warpred[w];
        g_partial[bid] = v;
        __threadfence();
        const unsigned int c = atomicAdd(&g_count, 1u);
        isLast = (c == (unsigned)(NBLOCKS - 1));
    }
    __syncthreads();

    // last block reduces partials, writes scalar, resets counter
    if (isLast) {
        float s = 0.f;
        for (int i = tid; i < NBLOCKS; i += NTHREADS) s += g_partial[i];
        #pragma unroll
        for (int o = 16; o > 0; o >>= 1) s += __shfl_xor_sync(0xffffffffu, s, o);
        if ((tid & 31) == 0) warpred[tid >> 5] = s;
        __syncthreads();
        if (tid == 0) {
            float t = 0.f;
            #pragma unroll
            for (int w = 0; w < NTHREADS / 32; ++w) t += warpred[w];
            out[0] = t / (float)NVOX;
            g_count = 0u;
        }
    }
}

extern "C" void kernel_launch(void* const* d_in, const int* in_sizes, int n_in,
                              void* d_out, int out_size)
{
    const float* Mp = (const float*)d_in[0];
    const float* Sp = (const float*)d_in[1];
    const float* Fp = (const float*)d_in[2];
    float* out = (float*)d_out;

    dim3 grid(GXD, GYD, GZD);   // (5, 24, 10) = 1200 blocks
    dim3 block(TX, TY, 1);      // (32, 8)
    demons_kernel<<<grid, block>>>(Mp, Sp, Fp, out);
}

// round 15
// speedup vs baseline: 1.2313x; 1.0667x over previous
#include <cuda_runtime.h>
#include <math.h>

// dims: (1,1,D=160,H=192,W=160), x fastest
#define DW 160
#define DH 192
#define DD 160
#define SLICE (DH*DW)
#define NVOX (DD*SLICE)

#define TX 32
#define TY 8
#define CZ 16
#define SMW (TX+2)
#define SMH (TY+2)
#define NTHREADS (TX*TY)
#define GXD (DW/TX)   // 5
#define GYD (DH/TY)   // 24
#define GZD (DD/CZ)   // 10
#define NBLOCKS (GXD*GYD*GZD)   // 1200
#define FEPS 1e-10f
#define FPI  3.14159265358979f

#define CELLS (SMH*SMW)          // 340
#define BUFBYTES (CELLS*8)       // one slice buffer
#define NSLICEBUF 10             // 5 double-buffers x 2 slices

typedef unsigned long long u64;

// packed (lo,hi) f32x2 helpers — FFMA2/FADD2 only reachable via PTX
__device__ __forceinline__ u64 pk2(float lo, float hi) {
    u64 r; asm("mov.b64 %0, {%1, %2};" : "=l"(r) : "f"(lo), "f"(hi)); return r;
}
__device__ __forceinline__ void upk2(u64 v, float& lo, float& hi) {
    asm("mov.b64 {%0, %1}, %2;" : "=f"(lo), "=f"(hi) : "l"(v));
}
__device__ __forceinline__ u64 fma2(u64 a, u64 b, u64 c) {
    u64 d; asm("fma.rn.f32x2 %0, %1, %2, %3;" : "=l"(d) : "l"(a), "l"(b), "l"(c)); return d;
}
__device__ __forceinline__ u64 add2(u64 a, u64 b) {
    u64 d; asm("add.rn.f32x2 %0, %1, %2;" : "=l"(d) : "l"(a), "l"(b)); return d;
}
#define NEG1P 0xBF800000BF800000ULL   // (-1.f, -1.f)
#define TWOP  0x4000000040000000ULL   // ( 2.f,  2.f)

// 4-byte async copy global -> shared
__device__ __forceinline__ void cpa4(unsigned sdst, const float* gsrc) {
    asm volatile("cp.async.ca.shared.global [%0], [%1], 4;" :: "r"(sdst), "l"(gsrc));
}
#define CP_COMMIT() asm volatile("cp.async.commit_group;" ::: "memory")
#define CP_WAIT3()  asm volatile("cp.async.wait_group 3;" ::: "memory")

__device__ float g_partial[NBLOCKS];
__device__ unsigned int g_count = 0;
__device__ float g_zerosrc[8] = {0,0,0,0,0,0,0,0};

// e = atan(fa/fb) - atan(na/nb) via tan-difference, ONE divide total.
// u = num/den folded as atan(min/max) + pi/2-fold; quadrant correction +/-pi.
__device__ __forceinline__ float atan_diff(float fa, float fb, float na, float nb, float w)
{
    // w = fb*nb passed in (shared across the two calls)
    const float num = fmaf(fa, nb, -na * fb);
    const float den = fmaf(fa, na, w);
    const float an = fabsf(num), ad = fabsf(den);
    const float t = __fdividef(fminf(an, ad), fmaxf(an, ad));   // in [0,1]
    const float z = t * t;
    float p = -0.0389929f;                    // deg-7 minimax, max err ~1e-4 rad
    p = fmaf(p, z, 0.1462766f);
    p = fmaf(p, z, -0.3211819f);
    p = fmaf(p, z, 0.9992150f);
    p = p * t;
    float r = (an > ad) ? (1.5707963f - p) : p;
    const unsigned sgn = (__float_as_uint(num) ^ __float_as_uint(den)) & 0x80000000u;
    r = __uint_as_float(__float_as_uint(r) | sgn);             // sign(num/den)
    const float c = (den * w < 0.f) ? copysignf(FPI, num * w) : 0.f;
    return r + c;
}

__global__ __launch_bounds__(NTHREADS, 4)
void demons_kernel(const float* __restrict__ Mp,
                   const float* __restrict__ Sp,
                   const float* __restrict__ Fp,
                   float* __restrict__ out)
{
    __shared__ u64 sm[NSLICEBUF][SMH][SMW];   // packed (M,S); slice j -> buffer j%10
    __shared__ float warpred[NTHREADS / 32];
    __shared__ bool isLast;

    const int tx = threadIdx.x, ty = threadIdx.y;
    const int tid = ty * TX + tx;
    const int x = blockIdx.x * TX + tx;
    const int y = blockIdx.y * TY + ty;
    const int zbase = blockIdx.z * CZ;
    const int bid = blockIdx.x + GXD * (blockIdx.y + GYD * blockIdx.z);

    // halo mapping (z-invariant): each thread covers <=2 of 340 slots
    const int ly0 = tid / SMW, lx0 = tid - ly0 * SMW;
    const int gy0 = blockIdx.y * TY + ly0 - 1;
    const int gx0 = blockIdx.x * TX + lx0 - 1;
    const bool v0 = ((unsigned)gy0 < (unsigned)DH) && ((unsigned)gx0 < (unsigned)DW);
    const int off0 = v0 ? (gy0 * DW + gx0) : 0;

    const int i1 = tid + NTHREADS;
    const bool has1 = (i1 < CELLS);
    const int ly1 = i1 / SMW, lx1 = i1 - ly1 * SMW;
    const int gy1 = blockIdx.y * TY + ly1 - 1;
    const int gx1 = blockIdx.x * TX + lx1 - 1;
    const bool v1 = has1 && ((unsigned)gy1 < (unsigned)DH) && ((unsigned)gx1 < (unsigned)DW);
    const int off1 = v1 ? (gy1 * DW + gx1) : 0;

    const unsigned sbase = (unsigned)__cvta_generic_to_shared(&sm[0][0][0]);
    const unsigned a0 = sbase + (unsigned)(ly0 * SMW + lx0) * 8u;
    const unsigned a1 = sbase + (unsigned)(ly1 * SMW + lx1) * 8u;
    const float* gz = g_zerosrc;

    // incremental pointers; start at slice zbase-1 (slice index 0)
    const float* pM0 = Mp + (zbase - 1) * SLICE + off0;
    const float* pS0 = Sp + (zbase - 1) * SLICE + off0;
    const float* pM1 = Mp + (zbase - 1) * SLICE + off1;
    const float* pS1 = Sp + (zbase - 1) * SLICE + off1;

    // prologue: 4 dbuf groups = slices 0..7 (z = zbase-1 .. zbase+6, upper always < DD)
    #pragma unroll
    for (int k = 0; k < 8; ++k) {
        const bool zin = (zbase - 1 + k >= 0);
        const unsigned ab0 = a0 + (unsigned)k * BUFBYTES;
        cpa4(ab0,      (v0 && zin) ? pM0 : gz);
        cpa4(ab0 + 4u, (v0 && zin) ? pS0 : gz);
        if (has1) {
            const unsigned ab1 = a1 + (unsigned)k * BUFBYTES;
            cpa4(ab1,      (v1 && zin) ? pM1 : gz);
            cpa4(ab1 + 4u, (v1 && zin) ? pS1 : gz);
        }
        if (k & 1) CP_COMMIT();
        pM0 += SLICE; pS0 += SLICE; pM1 += SLICE; pS1 += SLICE;
    }

    // flow registers: F0 serves even emit slices, F1 odd — no rotation MOVs.
    const float* pF0 = Fp + zbase * SLICE + y * DW + x;
    const float* pF1 = pF0 + SLICE;
    float F0x = __ldg(pF0), F0y = __ldg(pF0 + NVOX), F0z = __ldg(pF0 + 2 * NVOX);
    pF0 += 2 * SLICE;
    float F1x = __ldg(pF1), F1y = __ldg(pF1 + NVOX), F1z = __ldg(pF1 + 2 * NVOX);
    pF1 += 2 * SLICE;

    // packed per-slice responses, register ring of 3; advances 2/step -> period 3 steps
    u64 A0, A1, A2, B0, B1, B2, C0, C1, C2, c1r, c2r;
    A0 = A1 = B0 = B1 = C0 = C1 = c1r = 0ULL;
    float acc = 0.f;

// one slice: y-first separable stencil from buffer byte-offset RB (0..9 buffers),
// emit for slice index J using flow registers FX/FY/FZ with reload pointer PFP
#define DO_SLICE(RBI, J, FX, FY, FZ, PFP) do {                                                  \
    const u64 av0 = sm[RBI][ty + 0][tx], av1 = sm[RBI][ty + 0][tx + 1], av2 = sm[RBI][ty + 0][tx + 2]; \
    const u64 qv0 = sm[RBI][ty + 1][tx], qv1 = sm[RBI][ty + 1][tx + 1], qv2 = sm[RBI][ty + 1][tx + 2]; \
    const u64 ev0 = sm[RBI][ty + 2][tx], ev1 = sm[RBI][ty + 2][tx + 1], ev2 = sm[RBI][ty + 2][tx + 2]; \
    const u64 ySm0 = fma2(TWOP, qv0, add2(av0, ev0));                                           \
    const u64 yDf0 = fma2(av0, NEG1P, ev0);                                                     \
    const u64 ySm1 = fma2(TWOP, qv1, add2(av1, ev1));                                           \
    const u64 yDf1 = fma2(av1, NEG1P, ev1);                                                     \
    const u64 ySm2 = fma2(TWOP, qv2, add2(av2, ev2));                                           \
    const u64 yDf2 = fma2(av2, NEG1P, ev2);                                                     \
    A2 = fma2(ySm0, NEG1P, ySm2);                 /* smooth_y x diff_x  */                      \
    B2 = fma2(TWOP, yDf1, add2(yDf0, yDf2));      /* diff_y   x smooth_x*/                      \
    C2 = add2(ySm1, add2(ySm0, ySm2));            /* smooth_y x box_x   */                      \
    c2r = qv1;                                                                                  \
    if ((J) >= 2) {                                                                             \
        const u64 Gx = add2(add2(A0, A1), A2);                                                  \
        const u64 Gy = add2(add2(B0, B1), B2);                                                  \
        const u64 Gz = fma2(C0, NEG1P, C2);                                                     \
        float Mcv, Scv; upk2(c1r, Mcv, Scv);                                                    \
        const float Id  = Mcv - Scv;                                                            \
        const float Id2 = fmaf(Id, Id, FEPS);                                                   \
        const u64 d = fma2(Gx, Gx, fma2(Gy, Gy, fma2(Gz, Gz, pk2(Id2, Id2))));                  \
        float dM, dS; upk2(d, dM, dS);                                                          \
        float Mx, Sx; upk2(Gx, Mx, Sx);                                                         \
        float My, Sy; upk2(Gy, My, Sy);                                                         \
        float Mz, Sz; upk2(Gz, Mz, Sz);                                                         \
        const float nx = fmaf(Sx, dM, Mx * dS);                                                 \
        const float ny = fmaf(Sy, dM, My * dS);                                                 \
        const float nz = fmaf(Sz, dM, Mz * dS);                                                 \
        const float FZe = FZ + FEPS;                                                            \
        const float w = FZe * nz;                                                               \
        const float d1 = atan_diff(FX, FZe, nx, nz, w);                                         \
        const float d2 = atan_diff(FY, FZe, ny, nz, w);                                         \
        acc = fmaf(d1, d1, acc);                                                                \
        acc = fmaf(d2, d2, acc);                                                                \
        if ((J) <= CZ - 1) {                                                                    \
            FX = __ldg(PFP);                                                                    \
            FY = __ldg(PFP + NVOX);                                                             \
            FZ = __ldg(PFP + 2 * NVOX);                                                         \
            PFP += 2 * SLICE;                                                                   \
        }                                                                                       \
    }                                                                                           \
    A0 = A1; A1 = A2;  B0 = B1; B1 = B2;                                                        \
    C0 = C1; C1 = C2;  c1r = c2r;                                                               \
} while (0)

    int rb = 0;   // read slice-buffer index (step s reads rb, rb+1)
    int wb = 8;   // write slice-buffer index (step s writes wb, wb+1)

    #pragma unroll 3
    for (int s = 0; s < 9; ++s) {               // 9 steps x 2 slices = 18 slices
        // dbuf group s complete (3 groups still in flight); sync releases last-read dbuf
        CP_WAIT3();
        __syncthreads();

        // prefetch slices 2s+8, 2s+9 (z = zbase+2s+7, +8) into wb, wb+1
        if (s <= 4) {
            const unsigned ab = a0 + (unsigned)wb * BUFBYTES;
            const bool zin0 = (zbase + 2 * s + 7 < DD);
            const bool zin1 = (zbase + 2 * s + 8 < DD);
            cpa4(ab,                 (v0 && zin0) ? pM0 : gz);
            cpa4(ab + 4u,            (v0 && zin0) ? pS0 : gz);
            cpa4(ab + BUFBYTES,      (v0 && zin1) ? (pM0 + SLICE) : gz);
            cpa4(ab + BUFBYTES + 4u, (v0 && zin1) ? (pS0 + SLICE) : gz);
            if (has1) {
                const unsigned ab1 = a1 + (unsigned)wb * BUFBYTES;
                cpa4(ab1,                 (v1 && zin0) ? pM1 : gz);
                cpa4(ab1 + 4u,            (v1 && zin0) ? pS1 : gz);
                cpa4(ab1 + BUFBYTES,      (v1 && zin1) ? (pM1 + SLICE) : gz);
                cpa4(ab1 + BUFBYTES + 4u, (v1 && zin1) ? (pS1 + SLICE) : gz);
            }
            pM0 += 2 * SLICE; pS0 += 2 * SLICE; pM1 += 2 * SLICE; pS1 += 2 * SLICE;
        }
        CP_COMMIT();

        DO_SLICE(rb,     2 * s,     F0x, F0y, F0z, pF0);
        DO_SLICE(rb + 1, 2 * s + 1, F1x, F1y, F1z, pF1);

        rb += 2; if (rb == NSLICEBUF) rb = 0;
        wb += 2; if (wb == NSLICEBUF) wb = 0;
    }
#undef DO_SLICE

    // block reduction: warp shuffle + smem
    #pragma unroll
    for (int o = 16; o > 0; o >>= 1) acc += __shfl_xor_sync(0xffffffffu, acc, o);
    if ((tid & 31) == 0) warpred[tid >> 5] = acc;
    __syncthreads();
    if (tid == 0) {
        float v = 0.f;
        #pragma unroll
        for (int w = 0; w < NTHREADS / 32; ++w) v += warpred[w];
        g_partial[bid] = v;
        __threadfence();
        const unsigned int c = atomicAdd(&g_count, 1u);
        isLast = (c == (unsigned)(NBLOCKS - 1));
    }
    __syncthreads();

    // last block reduces partials, writes scalar, resets counter
    if (isLast) {
        float s = 0.f;
        for (int i = tid; i < NBLOCKS; i += NTHREADS) s += g_partial[i];
        #pragma unroll
        for (int o = 16; o > 0; o >>= 1) s += __shfl_xor_sync(0xffffffffu, s, o);
        if ((tid & 31) == 0) warpred[tid >> 5] = s;
        __syncthreads();
        if (tid == 0) {
            float t = 0.f;
            #pragma unroll
            for (int w = 0; w < NTHREADS / 32; ++w) t += warpred[w];
            out[0] = t / (float)NVOX;
            g_count = 0u;
        }
    }
}

extern "C" void kernel_launch(void* const* d_in, const int* in_sizes, int n_in,
                              void* d_out, int out_size)
{
    const float* Mp = (const float*)d_in[0];
    const float* Sp = (const float*)d_in[1];
    const float* Fp = (const float*)d_in[2];
    float* out = (float*)d_out;

    dim3 grid(GXD, GYD, GZD);   // (5, 24, 10) = 1200 blocks
    dim3 block(TX, TY, 1);      // (32, 8)
    demons_kernel<<<grid, block>>>(Mp, Sp, Fp, out);
}

// round 16
// speedup vs baseline: 1.2323x; 1.0008x over previous
#include <cuda_runtime.h>
#include <math.h>

// dims: (1,1,D=160,H=192,W=160), x fastest
#define DW 160
#define DH 192
#define DD 160
#define SLICE (DH*DW)
#define NVOX (DD*SLICE)

#define TX 32
#define TY 8
#define CZ 16
#define SMW (TX+2)
#define SMH (TY+2)
#define NTHREADS (TX*TY)
#define GXD (DW/TX)   // 5
#define GYD (DH/TY)   // 24
#define GZD (DD/CZ)   // 10
#define NBLOCKS (GXD*GYD*GZD)   // 1200
#define FEPS 1e-10f
#define FPI  3.14159265358979f

#define CELLS (SMH*SMW)          // 340
#define BUFBYTES (CELLS*8)       // one slice buffer
#define NSLICEBUF 12             // 4 groups x 3 slices

typedef unsigned long long u64;

// packed (lo,hi) f32x2 helpers — FFMA2/FADD2 only reachable via PTX
__device__ __forceinline__ u64 pk2(float lo, float hi) {
    u64 r; asm("mov.b64 %0, {%1, %2};" : "=l"(r) : "f"(lo), "f"(hi)); return r;
}
__device__ __forceinline__ void upk2(u64 v, float& lo, float& hi) {
    asm("mov.b64 {%0, %1}, %2;" : "=f"(lo), "=f"(hi) : "l"(v));
}
__device__ __forceinline__ u64 fma2(u64 a, u64 b, u64 c) {
    u64 d; asm("fma.rn.f32x2 %0, %1, %2, %3;" : "=l"(d) : "l"(a), "l"(b), "l"(c)); return d;
}
__device__ __forceinline__ u64 add2(u64 a, u64 b) {
    u64 d; asm("add.rn.f32x2 %0, %1, %2;" : "=l"(d) : "l"(a), "l"(b)); return d;
}
#define NEG1P 0xBF800000BF800000ULL   // (-1.f, -1.f)
#define TWOP  0x4000000040000000ULL   // ( 2.f,  2.f)

// 4-byte async copy global -> shared
__device__ __forceinline__ void cpa4(unsigned sdst, const float* gsrc) {
    asm volatile("cp.async.ca.shared.global [%0], [%1], 4;" :: "r"(sdst), "l"(gsrc));
}
#define CP_COMMIT() asm volatile("cp.async.commit_group;" ::: "memory")
#define CP_WAIT2()  asm volatile("cp.async.wait_group 2;" ::: "memory")

__device__ float g_partial[NBLOCKS];
__device__ unsigned int g_count = 0;
__device__ float g_zerosrc[8] = {0,0,0,0,0,0,0,0};

// e = atan(fa/fb) - atan(na/nb) via tan-difference, ONE divide, sign-bit quadrant fix.
__device__ __forceinline__ float atan_diff(float fa, float fb, float na, float nb, float w)
{
    const float num = fmaf(fa, nb, -na * fb);
    const float den = fmaf(fa, na, w);
    const float an = fabsf(num), ad = fabsf(den);
    const float t = __fdividef(fminf(an, ad), fmaxf(an, ad));   // in [0,1]
    const float z = t * t;
    float p = -0.0389929f;                    // deg-7 minimax, max err ~1e-4 rad
    p = fmaf(p, z, 0.1462766f);
    p = fmaf(p, z, -0.3211819f);
    p = fmaf(p, z, 0.9992150f);
    p = p * t;
    float r = (an > ad) ? (1.5707963f - p) : p;
    const unsigned un = __float_as_uint(num);
    const unsigned ud = __float_as_uint(den);
    const unsigned uw = __float_as_uint(w);
    r = __uint_as_float(__float_as_uint(r) | ((un ^ ud) & 0x80000000u));   // sign(num/den)
    // den*w < 0 (sign-bit test) -> add pi with sign(num*w)
    const float c = ((ud ^ uw) & 0x80000000u)
                  ? __uint_as_float(0x40490FDBu | ((un ^ uw) & 0x80000000u)) : 0.f;
    return r + c;
}

__global__ __launch_bounds__(NTHREADS, 4)
void demons_kernel(const float* __restrict__ Mp,
                   const float* __restrict__ Sp,
                   const float* __restrict__ Fp,
                   float* __restrict__ out)
{
    __shared__ u64 sm[NSLICEBUF][SMH][SMW];   // packed (M,S); slice k -> buffer k%12
    __shared__ float warpred[NTHREADS / 32];
    __shared__ bool isLast;

    const int tx = threadIdx.x, ty = threadIdx.y;
    const int tid = ty * TX + tx;
    const int x = blockIdx.x * TX + tx;
    const int y = blockIdx.y * TY + ty;
    const int zbase = blockIdx.z * CZ;
    const int bid = blockIdx.x + GXD * (blockIdx.y + GYD * blockIdx.z);

    // halo mapping (z-invariant): each thread covers <=2 of 340 slots
    const int ly0 = tid / SMW, lx0 = tid - ly0 * SMW;
    const int gy0 = blockIdx.y * TY + ly0 - 1;
    const int gx0 = blockIdx.x * TX + lx0 - 1;
    const bool v0 = ((unsigned)gy0 < (unsigned)DH) && ((unsigned)gx0 < (unsigned)DW);
    const int off0 = v0 ? (gy0 * DW + gx0) : 0;

    const int i1 = tid + NTHREADS;
    const bool has1 = (i1 < CELLS);
    const int ly1 = i1 / SMW, lx1 = i1 - ly1 * SMW;
    const int gy1 = blockIdx.y * TY + ly1 - 1;
    const int gx1 = blockIdx.x * TX + lx1 - 1;
    const bool v1 = has1 && ((unsigned)gy1 < (unsigned)DH) && ((unsigned)gx1 < (unsigned)DW);
    const int off1 = v1 ? (gy1 * DW + gx1) : 0;

    const unsigned sbase = (unsigned)__cvta_generic_to_shared(&sm[0][0][0]);
    const unsigned a0 = sbase + (unsigned)(ly0 * SMW + lx0) * 8u;
    const unsigned a1 = sbase + (unsigned)(ly1 * SMW + lx1) * 8u;
    const float* gz = g_zerosrc;

    // incremental pointers; start at slice zbase-1 (slice index 0)
    const float* pM0 = Mp + (zbase - 1) * SLICE + off0;
    const float* pS0 = Sp + (zbase - 1) * SLICE + off0;
    const float* pM1 = Mp + (zbase - 1) * SLICE + off1;
    const float* pS1 = Sp + (zbase - 1) * SLICE + off1;

    // prologue: 3 groups x 3 slices = slices 0..8 (z = zbase-1 .. zbase+7, upper < DD)
    #pragma unroll
    for (int k = 0; k < 9; ++k) {
        const bool zin = (zbase - 1 + k >= 0);
        const unsigned ab0 = a0 + (unsigned)k * BUFBYTES;
        cpa4(ab0,      (v0 && zin) ? pM0 : gz);
        cpa4(ab0 + 4u, (v0 && zin) ? pS0 : gz);
        if (has1) {
            const unsigned ab1 = a1 + (unsigned)k * BUFBYTES;
            cpa4(ab1,      (v1 && zin) ? pM1 : gz);
            cpa4(ab1 + 4u, (v1 && zin) ? pS1 : gz);
        }
        if (k % 3 == 2) CP_COMMIT();
        pM0 += SLICE; pS0 += SLICE; pM1 += SLICE; pS1 += SLICE;
    }

    // flow: 3 residue sets (J mod 3), each reloads its own z+3 — rotation-free.
    // Base pointer + 32-bit element offsets to limit register state.
    const float* pFb = Fp + y * DW + x;
    int iF0 = (zbase + 1) * SLICE;   // serves J=3,6,...  (z = zbase+1, +4, ...)
    int iF1 = (zbase + 2) * SLICE;   // serves J=4,7,...
    int iF2 = zbase * SLICE;         // serves J=2,5,...
    float F0x = __ldg(pFb + iF0), F0y = __ldg(pFb + iF0 + NVOX), F0z = __ldg(pFb + iF0 + 2 * NVOX);
    iF0 += 3 * SLICE;
    float F1x = __ldg(pFb + iF1), F1y = __ldg(pFb + iF1 + NVOX), F1z = __ldg(pFb + iF1 + 2 * NVOX);
    iF1 += 3 * SLICE;
    float F2x = __ldg(pFb + iF2), F2y = __ldg(pFb + iF2 + NVOX), F2z = __ldg(pFb + iF2 + 2 * NVOX);
    iF2 += 3 * SLICE;

    // packed per-slice responses, register ring of 3; advances 3/step -> period 1 step
    u64 A0, A1, A2, B0, B1, B2, C0, C1, C2, c1r, c2r;
    A0 = A1 = B0 = B1 = C0 = C1 = c1r = 0ULL;
    float acc = 0.f;

// one slice: y-first separable stencil from buffer index RBI, emit for slice index J
// using flow registers FX/FY/FZ with reload offset IDX
#define DO_SLICE(RBI, J, FX, FY, FZ, IDX) do {                                                  \
    const u64 av0 = sm[RBI][ty + 0][tx], av1 = sm[RBI][ty + 0][tx + 1], av2 = sm[RBI][ty + 0][tx + 2]; \
    const u64 qv0 = sm[RBI][ty + 1][tx], qv1 = sm[RBI][ty + 1][tx + 1], qv2 = sm[RBI][ty + 1][tx + 2]; \
    const u64 ev0 = sm[RBI][ty + 2][tx], ev1 = sm[RBI][ty + 2][tx + 1], ev2 = sm[RBI][ty + 2][tx + 2]; \
    const u64 ySm0 = fma2(TWOP, qv0, add2(av0, ev0));                                           \
    const u64 yDf0 = fma2(av0, NEG1P, ev0);                                                     \
    const u64 ySm1 = fma2(TWOP, qv1, add2(av1, ev1));                                           \
    const u64 yDf1 = fma2(av1, NEG1P, ev1);                                                     \
    const u64 ySm2 = fma2(TWOP, qv2, add2(av2, ev2));                                           \
    const u64 yDf2 = fma2(av2, NEG1P, ev2);                                                     \
    A2 = fma2(ySm0, NEG1P, ySm2);                 /* smooth_y x diff_x  */                      \
    B2 = fma2(TWOP, yDf1, add2(yDf0, yDf2));      /* diff_y   x smooth_x*/                      \
    C2 = add2(ySm1, add2(ySm0, ySm2));            /* smooth_y x box_x   */                      \
    c2r = qv1;                                                                                  \
    if ((J) >= 2) {                                                                             \
        const u64 Gx = add2(add2(A0, A1), A2);                                                  \
        const u64 Gy = add2(add2(B0, B1), B2);                                                  \
        const u64 Gz = fma2(C0, NEG1P, C2);                                                     \
        float Mcv, Scv; upk2(c1r, Mcv, Scv);                                                    \
        const float Id  = Mcv - Scv;                                                            \
        const float Id2 = fmaf(Id, Id, FEPS);                                                   \
        const u64 d = fma2(Gx, Gx, fma2(Gy, Gy, fma2(Gz, Gz, pk2(Id2, Id2))));                  \
        float dM, dS; upk2(d, dM, dS);                                                          \
        float Mx, Sx; upk2(Gx, Mx, Sx);                                                         \
        float My, Sy; upk2(Gy, My, Sy);                                                         \
        float Mz, Sz; upk2(Gz, Mz, Sz);                                                         \
        const float nx = fmaf(Sx, dM, Mx * dS);                                                 \
        const float ny = fmaf(Sy, dM, My * dS);                                                 \
        const float nz = fmaf(Sz, dM, Mz * dS);                                                 \
        const float FZe = FZ + FEPS;                                                            \
        const float w = FZe * nz;                                                               \
        const float d1 = atan_diff(FX, FZe, nx, nz, w);                                         \
        const float d2 = atan_diff(FY, FZe, ny, nz, w);                                         \
        acc = fmaf(d1, d1, acc);                                                                \
        acc = fmaf(d2, d2, acc);                                                                \
        if ((J) <= CZ - 2) {                                                                    \
            FX = __ldg(pFb + IDX);                                                              \
            FY = __ldg(pFb + IDX + NVOX);                                                       \
            FZ = __ldg(pFb + IDX + 2 * NVOX);                                                   \
            IDX += 3 * SLICE;                                                                   \
        }                                                                                       \
    }                                                                                           \
    A0 = A1; A1 = A2;  B0 = B1; B1 = B2;                                                        \
    C0 = C1; C1 = C2;  c1r = c2r;                                                               \
} while (0)

    #pragma unroll 2
    for (int s = 0; s < 6; ++s) {               // 6 steps x 3 slices = 18 slices
        // group s complete (2 groups may remain in flight)
        CP_WAIT2();
        __syncthreads();

        // prefetch group s+3 = slices 9+3s..11+3s (z = zbase+8+3s..+10+3s)
        if (s <= 2) {
            const int wb = ((s + 3) & 3) * 3;
            #pragma unroll
            for (int kk = 0; kk < 3; ++kk) {
                const bool zin = (zbase + 8 + 3 * s + kk < DD);
                const unsigned ab0 = a0 + (unsigned)(wb + kk) * BUFBYTES;
                cpa4(ab0,      (v0 && zin) ? (pM0 + kk * SLICE) : gz);
                cpa4(ab0 + 4u, (v0 && zin) ? (pS0 + kk * SLICE) : gz);
                if (has1) {
                    const unsigned ab1 = a1 + (unsigned)(wb + kk) * BUFBYTES;
                    cpa4(ab1,      (v1 && zin) ? (pM1 + kk * SLICE) : gz);
                    cpa4(ab1 + 4u, (v1 && zin) ? (pS1 + kk * SLICE) : gz);
                }
            }
            pM0 += 3 * SLICE; pS0 += 3 * SLICE; pM1 += 3 * SLICE; pS1 += 3 * SLICE;
        }
        CP_COMMIT();

        const int rb = (s & 3) * 3;             // read buffers rb, rb+1, rb+2
        DO_SLICE(rb,     3 * s,     F0x, F0y, F0z, iF0);
        DO_SLICE(rb + 1, 3 * s + 1, F1x, F1y, F1z, iF1);
        DO_SLICE(rb + 2, 3 * s + 2, F2x, F2y, F2z, iF2);
    }
#undef DO_SLICE

    // block reduction: warp shuffle + smem
    #pragma unroll
    for (int o = 16; o > 0; o >>= 1) acc += __shfl_xor_sync(0xffffffffu, acc, o);
    if ((tid & 31) == 0) warpred[tid >> 5] = acc;
    __syncthreads();
    if (tid == 0) {
        float v = 0.f;
        #pragma unroll
        for (int w = 0; w < NTHREADS / 32; ++w) v += warpred[w];
        g_partial[bid] = v;
        __threadfence();
        const unsigned int c = atomicAdd(&g_count, 1u);
        isLast = (c == (unsigned)(NBLOCKS - 1));
    }
    __syncthreads();

    // last block reduces partials, writes scalar, resets counter
    if (isLast) {
        float s = 0.f;
        for (int i = tid; i < NBLOCKS; i += NTHREADS) s += g_partial[i];
        #pragma unroll
        for (int o = 16; o > 0; o >>= 1) s += __shfl_xor_sync(0xffffffffu, s, o);
        if ((tid & 31) == 0) warpred[tid >> 5] = s;
        __syncthreads();
        if (tid == 0) {
            float t = 0.f;
            #pragma unroll
            for (int w = 0; w < NTHREADS / 32; ++w) t += warpred[w];
            out[0] = t / (float)NVOX;
            g_count = 0u;
        }
    }
}

extern "C" void kernel_launch(void* const* d_in, const int* in_sizes, int n_in,
                              void* d_out, int out_size)
{
    const float* Mp = (const float*)d_in[0];
    const float* Sp = (const float*)d_in[1];
    const float* Fp = (const float*)d_in[2];
    float* out = (float*)d_out;

    dim3 grid(GXD, GYD, GZD);   // (5, 24, 10) = 1200 blocks
    dim3 block(TX, TY, 1);      // (32, 8)
    demons_kernel<<<grid, block>>>(Mp, Sp, Fp, out);
}